// round 4
// baseline (speedup 1.0000x reference)
#include <cuda_runtime.h>
#include <cuda_bf16.h>
#include <math.h>
#include <stdint.h>

#define MAXN 20000
#define MAXE 320000

// ---------------- device scratch (no allocs allowed) ----------------
__device__ int   g_is64;
__device__ int   g_src[MAXE];
__device__ int   g_dst[MAXE];
__device__ int   g_esrc[MAXE];
__device__ float g_ewn[MAXE];
__device__ float g_deg[MAXN];
__device__ float g_dinv[MAXN];
__device__ int   g_cnt[MAXN];
__device__ int   g_rowptr[MAXN + 1];
__device__ int   g_cursor[MAXN];
__device__ int   g_part[32];
__device__ int   g_off2[32];
__device__ int   g_total;
__device__ float g_Phc[MAXN * 256];               // [P_h | P_c]
__device__ float g_base[(long long)MAXN * 512];   // permuted gate layout
__device__ float g_h[MAXN * 128];
__device__ float g_c[MAXN * 128];
__device__ float g_z[MAXN * 128];
// bf16-split transposed weights
// W_cell: [m in {0,1}][p = permuted col 0..511][k 0..127], perm p = t*128 + j*4 + q
__device__ __nv_bfloat16 g_WTh[2 * 512 * 128];
__device__ __nv_bfloat16 g_WTl[2 * 512 * 128];
// W_init: [p 0..255][k 0..255]
__device__ __nv_bfloat16 g_WIh[256 * 256];
__device__ __nv_bfloat16 g_WIl[256 * 256];

// ---------------- helpers ----------------
__device__ __forceinline__ float tanhA(float x) {
    float r; asm("tanh.approx.f32 %0, %1;" : "=f"(r) : "f"(x)); return r;
}
__device__ __forceinline__ float sigA(float x) {
    return fmaf(tanhA(0.5f * x), 0.5f, 0.5f);
}
__device__ __forceinline__ uint32_t smem_u32(const void* p) {
    uint32_t a;
    asm("{ .reg .u64 t; cvta.to.shared.u64 t, %1; cvt.u32.u64 %0, t; }" : "=r"(a) : "l"(p));
    return a;
}

#define LDSM4(r0, r1, r2, r3, a) \
    asm volatile("ldmatrix.sync.aligned.m8n8.x4.shared.b16 {%0,%1,%2,%3}, [%4];" \
        : "=r"(r0), "=r"(r1), "=r"(r2), "=r"(r3) : "r"(a))

#define MMA16816(d, a, b) \
    asm volatile("mma.sync.aligned.m16n8k16.row.col.f32.bf16.bf16.f32 " \
        "{%0,%1,%2,%3}, {%4,%5,%6,%7}, {%8,%9}, {%0,%1,%2,%3};" \
        : "+f"((d)[0]), "+f"((d)[1]), "+f"((d)[2]), "+f"((d)[3]) \
        : "r"((a)[0]), "r"((a)[1]), "r"((a)[2]), "r"((a)[3]), "r"((b)[0]), "r"((b)[1]))

__device__ __forceinline__ void split8(const float* v, uint4& hv, uint4& lv) {
    unsigned short* hp = (unsigned short*)&hv;
    unsigned short* lp = (unsigned short*)&lv;
#pragma unroll
    for (int i = 0; i < 8; i++) {
        __nv_bfloat16 hb = __float2bfloat16_rn(v[i]);
        float lf = v[i] - __bfloat162float(hb);
        __nv_bfloat16 lb = __float2bfloat16_rn(lf);
        hp[i] = *(unsigned short*)&hb;
        lp[i] = *(unsigned short*)&lb;
    }
}

// ---------------- setup kernels ----------------
__global__ void k_init(int n) {
    int i = blockIdx.x * blockDim.x + threadIdx.x;
    if (i < n) { g_deg[i] = 0.f; g_cnt[i] = 0; }
    if (i == 0) g_is64 = 1;
}

__global__ void k_detect(const unsigned int* __restrict__ w) {
    unsigned int v = w[2 * threadIdx.x + 1];
    if (v != 0u) g_is64 = 0;
}

__global__ void k_build(const void* __restrict__ ei, const float* __restrict__ ea, int E) {
    int e = blockIdx.x * blockDim.x + threadIdx.x;
    if (e >= E) return;
    int s, d;
    if (g_is64) {
        const long long* p = (const long long*)ei;
        s = (int)p[e]; d = (int)p[E + e];
    } else {
        const int* p = (const int*)ei;
        s = p[e]; d = p[E + e];
    }
    g_src[e] = s; g_dst[e] = d;
    atomicAdd(&g_deg[d], ea[e]);
    atomicAdd(&g_cnt[d], 1);
}

__global__ void k_dinv(int n) {
    int i = blockIdx.x * blockDim.x + threadIdx.x;
    if (i < n) g_dinv[i] = rsqrtf(g_deg[i] + 1.0f);
}

// hierarchical scan: per-block local exclusive scan + partials
__global__ void k_scan1(int n) {
    __shared__ int s[1024];
    int i = blockIdx.x * 1024 + threadIdx.x;
    int v = (i < n) ? g_cnt[i] : 0;
    s[threadIdx.x] = v;
    __syncthreads();
    for (int off = 1; off < 1024; off <<= 1) {
        int t = (threadIdx.x >= off) ? s[threadIdx.x - off] : 0;
        __syncthreads();
        s[threadIdx.x] += t;
        __syncthreads();
    }
    if (i <= n && i < (blockIdx.x + 1) * 1024 && i < n + 1) {
        if (i < n) g_rowptr[i] = s[threadIdx.x] - v;   // local exclusive
    }
    if (threadIdx.x == 1023) g_part[blockIdx.x] = s[1023];
}

__global__ void k_scan2(int nb) {
    int tid = threadIdx.x;                 // 32 threads
    int v = (tid < nb) ? g_part[tid] : 0;
    int incl = v;
    for (int o = 1; o < 32; o <<= 1) {
        int t = __shfl_up_sync(0xffffffffu, incl, o);
        if (tid >= o) incl += t;
    }
    if (tid < nb) g_off2[tid] = incl - v;
    if (tid == 31) g_total = incl;
}

__global__ void k_scan3(int n) {
    int i = blockIdx.x * 1024 + threadIdx.x;
    if (i < n) {
        int val = g_rowptr[i] + g_off2[blockIdx.x];
        g_rowptr[i] = val;
        g_cursor[i] = val;
    }
    if (i == 0) g_rowptr[n] = g_total;
}

__global__ void k_scatter(const float* __restrict__ ea, int E) {
    int e = blockIdx.x * blockDim.x + threadIdx.x;
    if (e >= E) return;
    int s = g_src[e], d = g_dst[e];
    int pos = atomicAdd(&g_cursor[d], 1);
    g_esrc[pos] = s;
    g_ewn[pos] = g_dinv[s] * ea[e] * g_dinv[d];
}

// W_cell transpose + gate-interleave permute + bf16 split
// permuted p = t*128 + j*4 + q  <->  orig col q*128 + t*32 + j
__global__ void k_splitW(const float* __restrict__ Wc) {
    int id = blockIdx.x * blockDim.x + threadIdx.x;   // 0 .. 131071
    int m = id >> 16;
    int rem = id & 65535;
    int p = rem >> 7;
    int k = rem & 127;
    int t = p >> 7, r7 = p & 127;
    int j = r7 >> 2, q = r7 & 3;
    int nc = q * 128 + t * 32 + j;
    float v = Wc[(long long)(m * 128 + k) * 512 + nc];
    __nv_bfloat16 hb = __float2bfloat16_rn(v);
    float lf = v - __bfloat162float(hb);
    g_WTh[id] = hb;
    g_WTl[id] = __float2bfloat16_rn(lf);
}

// W_init transpose + bf16 split: [p][k] = Wi[k][p]
__global__ void k_splitWi(const float* __restrict__ Wi) {
    int id = blockIdx.x * blockDim.x + threadIdx.x;   // 0 .. 65535
    int p = id >> 8;
    int k = id & 255;
    float v = Wi[(long long)k * 256 + p];
    __nv_bfloat16 hb = __float2bfloat16_rn(v);
    float lf = v - __bfloat162float(hb);
    g_WIh[id] = hb;
    g_WIl[id] = __float2bfloat16_rn(lf);
}

// ---------------- sparse propagate ----------------
__global__ void k_prop(const float* __restrict__ x, int ldx,
                       float* __restrict__ out, int ldo, int n) {
    int v = (blockIdx.x * blockDim.x + threadIdx.x) >> 5;
    int lane = threadIdx.x & 31;
    if (v >= n) return;
    int beg = g_rowptr[v], end = g_rowptr[v + 1];
    float ax = 0.f, ay = 0.f, az = 0.f, aw = 0.f;
    int e = beg;
    for (; e + 1 < end; e += 2) {
        int s0 = g_esrc[e], s1 = g_esrc[e + 1];
        float w0 = g_ewn[e], w1 = g_ewn[e + 1];
        float4 v0 = __ldg((const float4*)(x + (long long)s0 * ldx) + lane);
        float4 v1 = __ldg((const float4*)(x + (long long)s1 * ldx) + lane);
        ax = fmaf(w0, v0.x, ax); ay = fmaf(w0, v0.y, ay);
        az = fmaf(w0, v0.z, az); aw = fmaf(w0, v0.w, aw);
        ax = fmaf(w1, v1.x, ax); ay = fmaf(w1, v1.y, ay);
        az = fmaf(w1, v1.z, az); aw = fmaf(w1, v1.w, aw);
    }
    if (e < end) {
        int s0 = g_esrc[e];
        float w0 = g_ewn[e];
        float4 v0 = __ldg((const float4*)(x + (long long)s0 * ldx) + lane);
        ax = fmaf(w0, v0.x, ax); ay = fmaf(w0, v0.y, ay);
        az = fmaf(w0, v0.z, az); aw = fmaf(w0, v0.w, aw);
    }
    float di = g_dinv[v];
    float w2 = di * di;
    float4 vv = __ldg((const float4*)(x + (long long)v * ldx) + lane);
    ax = fmaf(w2, vv.x, ax); ay = fmaf(w2, vv.y, ay);
    az = fmaf(w2, vv.z, az); aw = fmaf(w2, vv.w, aw);
    float4 o; o.x = ax; o.y = ay; o.z = az; o.w = aw;
    *((float4*)(out + (long long)v * ldo) + lane) = o;
}

// ---------------- tensor-core GEMM (mma.sync bf16 split-3) ----------------
// C[128 x 128] = X[m0:m0+128, 0:K] @ B[n0:n0+128, 0:K]^T   (B row-major [P][K])
// smem (dynamic 128KB): Ahi[0,32K) Alo[32K,64K) Bhi[64K,96K) Blo[96K,128K)
// rows 256B (128 bf16), 16B granules swizzled: off = row*256 + ((g ^ (row&7))<<4)
// mode 0: o512[r*512 + t*128 + c] = D + bc[orig col]        (base precompute, permuted)
// mode 1: LSTM gates: D + base; update g_h/g_c; write oseq  (permuted gate layout)
// mode 2: init: elu(D + bi[col]) -> g_h (cols<128) / g_c
__global__ void __launch_bounds__(256, 1)
k_mma(const float* __restrict__ X, int ldx,
      const __nv_bfloat16* __restrict__ Bh, const __nv_bfloat16* __restrict__ Bl,
      int K, const float* __restrict__ aux, float* __restrict__ o512,
      float* __restrict__ oseq, int n, int mode) {
    extern __shared__ char sm[];
    const uint32_t sb = smem_u32(sm);
    const int tid = threadIdx.x;
    const int lane = tid & 31;
    const int wid = tid >> 5;
    const int m0 = blockIdx.x * 128;
    const int t = blockIdx.y;
    const int mw = (wid & 3) * 32;
    const int nw = (wid >> 2) * 64;

    float acc[2][8][4];
#pragma unroll
    for (int i = 0; i < 2; i++)
#pragma unroll
        for (int j = 0; j < 8; j++)
#pragma unroll
            for (int q = 0; q < 4; q++) acc[i][j][q] = 0.f;

    const int nslab = K >> 7;
    for (int ks = 0; ks < nslab; ks++) {
        if (ks) __syncthreads();
        // ---- stage A (fp32 -> bf16 hi/lo) ----
#pragma unroll
        for (int it = 0; it < 8; it++) {
            int id = tid + it * 256;
            int m = id >> 4, g = id & 15;
            int grow = m0 + m;
            float v[8];
            if (grow < n) {
                const float4* xp = (const float4*)(X + (size_t)grow * ldx + ks * 128 + g * 8);
                float4 p0 = __ldg(xp), p1 = __ldg(xp + 1);
                v[0] = p0.x; v[1] = p0.y; v[2] = p0.z; v[3] = p0.w;
                v[4] = p1.x; v[5] = p1.y; v[6] = p1.z; v[7] = p1.w;
            } else {
#pragma unroll
                for (int q = 0; q < 8; q++) v[q] = 0.f;
            }
            uint4 hv, lv;
            split8(v, hv, lv);
            uint32_t off = m * 256 + ((g ^ (m & 7)) << 4);
            *(uint4*)(sm + off) = hv;
            *(uint4*)(sm + 32768 + off) = lv;
        }
        // ---- stage B (pre-split bf16) ----
#pragma unroll
        for (int it = 0; it < 8; it++) {
            int id = tid + it * 256;
            int p = id >> 4, g = id & 15;
            size_t src = (size_t)(t * 128 + p) * K + ks * 128 + g * 8;
            uint4 hv = __ldg((const uint4*)(Bh + src));
            uint4 lv = __ldg((const uint4*)(Bl + src));
            uint32_t off = p * 256 + ((g ^ (p & 7)) << 4);
            *(uint4*)(sm + 65536 + off) = hv;
            *(uint4*)(sm + 98304 + off) = lv;
        }
        __syncthreads();
        // ---- compute 8 k16 chunks ----
#pragma unroll
        for (int kc = 0; kc < 8; kc++) {
            uint32_t ah[2][4], al[2][4];
#pragma unroll
            for (int mf = 0; mf < 2; mf++) {
                int row = mw + mf * 16 + (lane & 15);
                int g = kc * 2 + (lane >> 4);
                uint32_t a = sb + row * 256 + ((g ^ (row & 7)) << 4);
                LDSM4(ah[mf][0], ah[mf][1], ah[mf][2], ah[mf][3], a);
                LDSM4(al[mf][0], al[mf][1], al[mf][2], al[mf][3], a + 32768);
            }
            uint32_t bh[8][2], bl[8][2];
#pragma unroll
            for (int bp = 0; bp < 4; bp++) {
                int p = nw + bp * 16 + ((lane >> 4) << 3) + (lane & 7);
                int g = kc * 2 + ((lane >> 3) & 1);
                uint32_t a = sb + 65536 + p * 256 + ((g ^ (p & 7)) << 4);
                uint32_t r0, r1, r2, r3;
                LDSM4(r0, r1, r2, r3, a);
                bh[2 * bp][0] = r0; bh[2 * bp][1] = r1;
                bh[2 * bp + 1][0] = r2; bh[2 * bp + 1][1] = r3;
                LDSM4(r0, r1, r2, r3, a + 32768);
                bl[2 * bp][0] = r0; bl[2 * bp][1] = r1;
                bl[2 * bp + 1][0] = r2; bl[2 * bp + 1][1] = r3;
            }
#pragma unroll
            for (int mf = 0; mf < 2; mf++)
#pragma unroll
                for (int nf = 0; nf < 8; nf++) {
                    MMA16816(acc[mf][nf], ah[mf], bh[nf]);
                    MMA16816(acc[mf][nf], ah[mf], bl[nf]);
                    MMA16816(acc[mf][nf], al[mf], bh[nf]);
                }
        }
    }

    // ---- epilogue ----
#pragma unroll
    for (int mf = 0; mf < 2; mf++) {
        int r0 = m0 + mw + mf * 16 + (lane >> 2);
        int r1 = r0 + 8;
#pragma unroll
        for (int nf = 0; nf < 8; nf++) {
            float d0 = acc[mf][nf][0], d1 = acc[mf][nf][1];
            float d2 = acc[mf][nf][2], d3 = acc[mf][nf][3];
            int c0 = nw + nf * 8 + (lane & 3) * 2;
            if (mode == 2) {
                int gc = t * 128 + c0;
                float2 bb = *(const float2*)(aux + gc);
                float* dst = (gc < 128) ? (g_h + gc) : (g_c + gc - 128);
                if (r0 < n) {
                    float e0 = d0 + bb.x, e1 = d1 + bb.y;
                    e0 = (e0 > 0.f) ? e0 : expm1f(e0);
                    e1 = (e1 > 0.f) ? e1 : expm1f(e1);
                    float2 o; o.x = e0; o.y = e1;
                    *(float2*)(dst + (size_t)r0 * 128) = o;
                }
                if (r1 < n) {
                    float e0 = d2 + bb.x, e1 = d3 + bb.y;
                    e0 = (e0 > 0.f) ? e0 : expm1f(e0);
                    e1 = (e1 > 0.f) ? e1 : expm1f(e1);
                    float2 o; o.x = e0; o.y = e1;
                    *(float2*)(dst + (size_t)r1 * 128) = o;
                }
            } else if (mode == 0) {
                int j = c0 >> 2, q = c0 & 3;
                float bb0 = aux[q * 128 + t * 32 + j];
                float bb1 = aux[(q + 1) * 128 + t * 32 + j];
                if (r0 < n) {
                    float2 o; o.x = d0 + bb0; o.y = d1 + bb1;
                    *(float2*)(o512 + (size_t)r0 * 512 + t * 128 + c0) = o;
                }
                if (r1 < n) {
                    float2 o; o.x = d2 + bb0; o.y = d3 + bb1;
                    *(float2*)(o512 + (size_t)r1 * 512 + t * 128 + c0) = o;
                }
            } else {
                float2 b0 = make_float2(0.f, 0.f), b1 = make_float2(0.f, 0.f);
                if (r0 < n) b0 = *(const float2*)(aux + (size_t)r0 * 512 + t * 128 + c0);
                if (r1 < n) b1 = *(const float2*)(aux + (size_t)r1 * 512 + t * 128 + c0);
                float v0 = d0 + b0.x, v1 = d1 + b0.y;
                float v2 = d2 + b1.x, v3 = d3 + b1.y;
                float u0 = __shfl_xor_sync(0xffffffffu, v0, 1);
                float u1 = __shfl_xor_sync(0xffffffffu, v1, 1);
                float u2 = __shfl_xor_sync(0xffffffffu, v2, 1);
                float u3 = __shfl_xor_sync(0xffffffffu, v3, 1);
                if (!(lane & 1)) {
                    // this lane: (i, f); partner: (o, g)
                    int j = c0 >> 2;
                    int hcol = t * 32 + j;
                    if (r0 < n) {
                        size_t ix = (size_t)r0 * 128 + hcol;
                        float cold = g_c[ix];
                        float cn = sigA(v1) * cold + sigA(v0) * tanhA(u1);
                        float hn = sigA(u0) * tanhA(cn);
                        g_c[ix] = cn; g_h[ix] = hn; oseq[ix] = hn;
                    }
                    if (r1 < n) {
                        size_t ix = (size_t)r1 * 128 + hcol;
                        float cold = g_c[ix];
                        float cn = sigA(v3) * cold + sigA(v2) * tanhA(u3);
                        float hn = sigA(u2) * tanhA(cn);
                        g_c[ix] = cn; g_h[ix] = hn; oseq[ix] = hn;
                    }
                }
            }
        }
    }
}

// ---------------- host launcher ----------------
extern "C" void kernel_launch(void* const* d_in, const int* in_sizes, int n_in,
                              void* d_out, int out_size) {
    const float* h  = (const float*)d_in[0];
    const float* c  = (const float*)d_in[1];
    const void*  ei = d_in[2];
    const float* ea = (const float*)d_in[3];
    const float* Wi = (const float*)d_in[4];
    const float* bi = (const float*)d_in[5];
    const float* Wc = (const float*)d_in[6];
    const float* bc = (const float*)d_in[7];
    float* out = (float*)d_out;

    int n   = in_sizes[0] / 128;
    int E   = in_sizes[3];
    int seq = out_size / (n * 128);

    static float* p_Phc = nullptr;
    static float* p_base = nullptr;
    static float* p_h = nullptr;
    static float* p_z = nullptr;
    static __nv_bfloat16* p_WTh = nullptr;
    static __nv_bfloat16* p_WTl = nullptr;
    static __nv_bfloat16* p_WIh = nullptr;
    static __nv_bfloat16* p_WIl = nullptr;
    if (!p_Phc) {
        cudaGetSymbolAddress((void**)&p_Phc, g_Phc);
        cudaGetSymbolAddress((void**)&p_base, g_base);
        cudaGetSymbolAddress((void**)&p_h, g_h);
        cudaGetSymbolAddress((void**)&p_z, g_z);
        cudaGetSymbolAddress((void**)&p_WTh, g_WTh);
        cudaGetSymbolAddress((void**)&p_WTl, g_WTl);
        cudaGetSymbolAddress((void**)&p_WIh, g_WIh);
        cudaGetSymbolAddress((void**)&p_WIl, g_WIl);
        cudaFuncSetAttribute(k_mma, cudaFuncAttributeMaxDynamicSharedMemorySize, 131072);
    }

    int nb256 = (n + 255) / 256;
    int eb256 = (E + 255) / 256;
    int nb1024 = (n + 1023) / 1024;
    int mtiles = (n + 127) / 128;
    int prop_blocks = (n * 32 + 255) / 256;
    size_t smem_sz = 131072;

    // ---- graph setup (per launch; deterministic) ----
    k_init<<<nb256, 256>>>(n);
    k_detect<<<1, 128>>>((const unsigned int*)ei);
    k_build<<<eb256, 256>>>(ei, ea, E);
    k_dinv<<<nb256, 256>>>(n);
    k_scan1<<<nb1024, 1024>>>(n);
    k_scan2<<<1, 32>>>(nb1024);
    k_scan3<<<nb1024, 1024>>>(n);
    k_scatter<<<eb256, 256>>>(ea, E);
    k_splitW<<<512, 256>>>(Wc);
    k_splitWi<<<256, 256>>>(Wi);

    // ---- loop-invariant precompute ----
    k_prop<<<prop_blocks, 256>>>(h, 128, p_Phc, 256, n);        // P_h
    k_prop<<<prop_blocks, 256>>>(c, 128, p_Phc + 128, 256, n);  // P_c
    // init: elu(Phc @ W_init + b_init) -> g_h, g_c
    k_mma<<<dim3(mtiles, 2), 256, smem_sz>>>(p_Phc, 256, p_WIh, p_WIl, 256,
                                             bi, nullptr, nullptr, n, 2);
    // base_perm = P_h @ Wc[0:128] + b_cell
    k_mma<<<dim3(mtiles, 4), 256, smem_sz>>>(p_Phc, 256, p_WTh, p_WTl, 128,
                                             bc, p_base, nullptr, n, 0);

    // ---- sequence ----
    for (int tt = 0; tt < seq; tt++) {
        k_prop<<<prop_blocks, 256>>>(p_h, 128, p_z, 128, n);
        k_mma<<<dim3(mtiles, 4), 256, smem_sz>>>(p_z, 128, p_WTh + 512 * 128, p_WTl + 512 * 128,
                                                 128, p_base, nullptr,
                                                 out + (long long)tt * n * 128, n, 1);
    }
}